// round 5
// baseline (speedup 1.0000x reference)
#include <cuda_runtime.h>
#include <cuda_bf16.h>
#include <math.h>

#define NN 100000
#define NF 64
#define NC 40
#define NE 1600000
#define SCAN_CHUNK 1024
#define NBLK_SCAN 98            // ceil(100000/1024)

// device-global scratch (allocation rules)
__device__ __align__(16) float g_y[NN * NC];   // x @ lin_l_w
__device__ __align__(16) float g_z[NN * NC];   // x @ lin_r_w + b
__device__ int g_cnt[NN];        // in-degree (histogram)
__device__ int g_off[NN];        // CSR row offsets (exclusive scan of cnt)
__device__ int g_cursor[NN];     // fill cursors
__device__ int g_csr[NE];        // edge sources grouped by dst
__device__ int g_bsums[128];     // scan block sums
__device__ int g_is64;           // index dtype flag

// ---------------------------------------------------------------------------
__global__ void k_detect(const int* __restrict__ idx32) {
    if (threadIdx.x == 0) {
        int odd_nonzero = 0;
        for (int i = 1; i < 128; i += 2)
            if (idx32[i] != 0) odd_nonzero++;
        g_is64 = (odd_nonzero == 0) ? 1 : 0;
    }
}

// ---------------------------------------------------------------------------
// K1: y = x@Wl, z = x@Wr + b; zero cnt.
// ---------------------------------------------------------------------------
__global__ void __launch_bounds__(256) k_gemm(const float* __restrict__ x,
                                              const float* __restrict__ wl,
                                              const float* __restrict__ bl,
                                              const float* __restrict__ wr) {
    __shared__ float s_wl[NF * NC];
    __shared__ float s_wr[NF * NC];
    __shared__ float s_b[NC];
    __shared__ float s_x[64][NF + 1];

    const int tid = threadIdx.x;
    for (int i = tid; i < NF * NC; i += 256) {
        s_wl[i] = wl[i];
        s_wr[i] = wr[i];
    }
    if (tid < NC) s_b[tid] = bl[tid];

    const int n0 = blockIdx.x * 64;
    for (int i = tid; i < 64 * NF; i += 256) {
        int r = i >> 6, k = i & 63;
        int n = n0 + r;
        s_x[r][k] = (n < NN) ? x[(size_t)n * NF + k] : 0.0f;
    }
    __syncthreads();

    for (int p = tid; p < 64 * NC; p += 256) {
        int r = p / NC, c = p % NC;
        int n = n0 + r;
        if (n >= NN) continue;
        float ya = 0.0f, za = 0.0f;
#pragma unroll
        for (int k = 0; k < NF; k++) {
            float xv = s_x[r][k];
            ya = fmaf(xv, s_wl[k * NC + c], ya);
            za = fmaf(xv, s_wr[k * NC + c], za);
        }
        g_y[n * NC + c] = ya;
        g_z[n * NC + c] = za + s_b[c];
        if (c == 0) g_cnt[n] = 0;
    }
}

// ---------------------------------------------------------------------------
// helpers to read dst/src under dtype flag
// ---------------------------------------------------------------------------
__device__ __forceinline__ int load_idx(const void* raw, long long pos) {
    int v;
    if (g_is64) v = (int)((const long long*)raw)[pos];
    else        v = ((const int*)raw)[pos];
    return min(max(v, 0), NN - 1);
}

// K2: degree histogram (int RED.ADD)
__global__ void __launch_bounds__(256) k_hist(const void* __restrict__ idx_raw) {
    int e = blockIdx.x * 256 + threadIdx.x;
    if (e >= NE) return;
    int dst = load_idx(idx_raw, (long long)NE + e);
    atomicAdd(&g_cnt[dst], 1);
}

// K3a: per-block (1024-elem) exclusive scan
__global__ void __launch_bounds__(256) k_scan1() {
    __shared__ int s[256];
    int base = blockIdx.x * SCAN_CHUNK + threadIdx.x * 4;
    int v0 = (base + 0 < NN) ? g_cnt[base + 0] : 0;
    int v1 = (base + 1 < NN) ? g_cnt[base + 1] : 0;
    int v2 = (base + 2 < NN) ? g_cnt[base + 2] : 0;
    int v3 = (base + 3 < NN) ? g_cnt[base + 3] : 0;
    int tsum = v0 + v1 + v2 + v3;
    s[threadIdx.x] = tsum;
    __syncthreads();
#pragma unroll
    for (int off = 1; off < 256; off <<= 1) {
        int t = (threadIdx.x >= off) ? s[threadIdx.x - off] : 0;
        __syncthreads();
        s[threadIdx.x] += t;
        __syncthreads();
    }
    int excl = s[threadIdx.x] - tsum;
    if (base + 0 < NN) g_off[base + 0] = excl;
    if (base + 1 < NN) g_off[base + 1] = excl + v0;
    if (base + 2 < NN) g_off[base + 2] = excl + v0 + v1;
    if (base + 3 < NN) g_off[base + 3] = excl + v0 + v1 + v2;
    if (threadIdx.x == 255) g_bsums[blockIdx.x] = s[255];
}

// K3b: scan block sums (1 block, 128 threads covers 98 blocks)
__global__ void k_scan2() {
    __shared__ int s[128];
    int tid = threadIdx.x;
    int v = (tid < NBLK_SCAN) ? g_bsums[tid] : 0;
    s[tid] = v;
    __syncthreads();
#pragma unroll
    for (int off = 1; off < 128; off <<= 1) {
        int t = (tid >= off) ? s[tid - off] : 0;
        __syncthreads();
        s[tid] += t;
        __syncthreads();
    }
    if (tid < NBLK_SCAN) g_bsums[tid] = s[tid] - v;
}

// K3c: finalize offsets + init cursors
__global__ void __launch_bounds__(256) k_scan3() {
    int n = blockIdx.x * 256 + threadIdx.x;
    if (n >= NN) return;
    int o = g_off[n] + g_bsums[n >> 10];
    g_off[n] = o;
    g_cursor[n] = o;
}

// K4: CSR fill
__global__ void __launch_bounds__(256) k_fill(const void* __restrict__ idx_raw) {
    int e = blockIdx.x * 256 + threadIdx.x;
    if (e >= NE) return;
    int src = load_idx(idx_raw, e);
    int dst = load_idx(idx_raw, (long long)NE + e);
    int pos = atomicAdd(&g_cursor[dst], 1);
    g_csr[pos] = src;
}

// ---------------------------------------------------------------------------
// K5: fused gather-reduce + mean + root-add + log_softmax. Warp per node.
// lanes: c0 = lane (0..31), c1 = lane+32 (lanes 0..7 active).
// ---------------------------------------------------------------------------
__global__ void __launch_bounds__(256) k_fused(float* __restrict__ out) {
    int gtid = blockIdx.x * 256 + threadIdx.x;
    int node = gtid >> 5;
    int lane = threadIdx.x & 31;
    if (node >= NN) return;

    int base = g_off[node];
    int deg  = g_cnt[node];

    float acc0 = 0.0f, acc1 = 0.0f;
    for (int j0 = 0; j0 < deg; j0 += 32) {
        int e = (j0 + lane < deg) ? g_csr[base + j0 + lane] : 0;
        int m = min(32, deg - j0);
        for (int k = 0; k < m; k++) {
            int src = __shfl_sync(0xFFFFFFFFu, e, k);
            const float* row = &g_y[src * NC];
            acc0 += row[lane];
            if (lane < 8) acc1 += row[32 + lane];
        }
    }

    float inv = 1.0f / fmaxf((float)deg, 1.0f);
    const float NEG = -3.0e38f;
    const float* zrow = &g_z[node * NC];
    float va = fmaf(acc0, inv, zrow[lane]);
    float vb = (lane < 8) ? fmaf(acc1, inv, zrow[32 + lane]) : NEG;

    float mx = fmaxf(va, vb);
#pragma unroll
    for (int off = 16; off > 0; off >>= 1)
        mx = fmaxf(mx, __shfl_xor_sync(0xFFFFFFFFu, mx, off));

    float s = __expf(va - mx) + ((lane < 8) ? __expf(vb - mx) : 0.0f);
#pragma unroll
    for (int off = 16; off > 0; off >>= 1)
        s += __shfl_xor_sync(0xFFFFFFFFu, s, off);

    float lse = mx + logf(s);
    out[node * NC + lane] = va - lse;
    if (lane < 8) out[node * NC + 32 + lane] = vb - lse;
}

extern "C" void kernel_launch(void* const* d_in, const int* in_sizes, int n_in,
                              void* d_out, int out_size) {
    const float* x   = (const float*)d_in[0];
    const void*  idx = d_in[1];
    const float* wl  = (const float*)d_in[2];
    const float* bl  = (const float*)d_in[3];
    const float* wr  = (const float*)d_in[4];
    float* out = (float*)d_out;

    k_detect<<<1, 32>>>((const int*)idx);
    k_gemm<<<(NN + 63) / 64, 256>>>(x, wl, bl, wr);
    k_hist<<<(NE + 255) / 256, 256>>>(idx);
    k_scan1<<<NBLK_SCAN, 256>>>();
    k_scan2<<<1, 128>>>();
    k_scan3<<<(NN + 255) / 256, 256>>>();
    k_fill<<<(NE + 255) / 256, 256>>>(idx);
    k_fused<<<(NN * 32 + 255) / 256, 256>>>(out);
}

// round 6
// speedup vs baseline: 1.7339x; 1.7339x over previous
#include <cuda_runtime.h>
#include <cuda_fp16.h>
#include <math.h>

#define NN 100000
#define NF 64
#define NC 40
#define NE 1600000
#define NODES_BLK 64
#define GEMM_THREADS 160          // 16 node-quads x 10 col-quads
#define NBLK_SCAN 98              // ceil(100000/1024)

// device-global scratch
__device__ __align__(16) __half2 g_yh[NN * 32];  // y = x@Wl, fp16, rows padded to 64 halves (128B)
__device__ __align__(16) float   g_z[NN * NC];   // z = x@Wr + b
__device__ int g_cnt[NN];
__device__ int g_off[NN];
__device__ int g_cursor[NN];
__device__ int g_csr[NE];
__device__ int g_bsums[128];
__device__ int g_is64;

// ---------------------------------------------------------------------------
// K0: detect index dtype + zero g_cnt.
// ---------------------------------------------------------------------------
__global__ void __launch_bounds__(256) k_prep(const int* __restrict__ idx32) {
    if (blockIdx.x == 0 && threadIdx.x == 0) {
        int odd_nonzero = 0;
        for (int i = 1; i < 128; i += 2)
            if (idx32[i] != 0) odd_nonzero++;
        g_is64 = (odd_nonzero == 0) ? 1 : 0;
    }
    int n = blockIdx.x * 256 + threadIdx.x;
    if (n < NN) g_cnt[n] = 0;
}

// ---------------------------------------------------------------------------
// K1: register-tiled dual GEMM. Block = 64 nodes x 40 cols.
// Thread = 4 nodes x 4 cols (float4 LDS on both operands).
// ---------------------------------------------------------------------------
__global__ void __launch_bounds__(GEMM_THREADS) k_gemm(const float* __restrict__ x,
                                                       const float* __restrict__ wl,
                                                       const float* __restrict__ bl,
                                                       const float* __restrict__ wr) {
    __shared__ float s_xT[NF][NODES_BLK];   // transposed x tile: [k][node]
    __shared__ float s_wl[NF * NC];
    __shared__ float s_wr[NF * NC];
    __shared__ float s_b[NC];

    const int tid = threadIdx.x;
    const int n0 = blockIdx.x * NODES_BLK;

    // weights (flat copy, coalesced)
    for (int i = tid; i < NF * NC; i += GEMM_THREADS) {
        s_wl[i] = wl[i];
        s_wr[i] = wr[i];
    }
    if (tid < NC) s_b[tid] = bl[tid];

    // x tile, transposed. 64 nodes x 16 float4. node fastest -> conflict-free STS.
    for (int i = tid; i < NODES_BLK * 16; i += GEMM_THREADS) {
        int node = i & (NODES_BLK - 1);
        int kq = i >> 6;
        int gn = n0 + node;
        float4 v = make_float4(0.f, 0.f, 0.f, 0.f);
        if (gn < NN) v = reinterpret_cast<const float4*>(x)[gn * 16 + kq];
        s_xT[kq * 4 + 0][node] = v.x;
        s_xT[kq * 4 + 1][node] = v.y;
        s_xT[kq * 4 + 2][node] = v.z;
        s_xT[kq * 4 + 3][node] = v.w;
    }
    __syncthreads();

    const int nq = tid / 10;        // 0..15
    const int cq = tid - nq * 10;   // 0..9

    float ay[4][4] = {}, az[4][4] = {};
#pragma unroll 4
    for (int k = 0; k < NF; k++) {
        const float4 xv  = *reinterpret_cast<const float4*>(&s_xT[k][nq * 4]);
        const float4 wl4 = *reinterpret_cast<const float4*>(&s_wl[k * NC + cq * 4]);
        const float4 wr4 = *reinterpret_cast<const float4*>(&s_wr[k * NC + cq * 4]);
        const float xs[4] = {xv.x, xv.y, xv.z, xv.w};
        const float ws[4] = {wl4.x, wl4.y, wl4.z, wl4.w};
        const float vs[4] = {wr4.x, wr4.y, wr4.z, wr4.w};
#pragma unroll
        for (int i = 0; i < 4; i++)
#pragma unroll
            for (int j = 0; j < 4; j++) {
                ay[i][j] = fmaf(xs[i], ws[j], ay[i][j]);
                az[i][j] = fmaf(xs[i], vs[j], az[i][j]);
            }
    }

#pragma unroll
    for (int i = 0; i < 4; i++) {
        int n = n0 + nq * 4 + i;
        if (n >= NN) continue;
        float4 zb;
        zb.x = az[i][0] + s_b[cq * 4 + 0];
        zb.y = az[i][1] + s_b[cq * 4 + 1];
        zb.z = az[i][2] + s_b[cq * 4 + 2];
        zb.w = az[i][3] + s_b[cq * 4 + 3];
        reinterpret_cast<float4*>(&g_z[n * NC])[cq] = zb;
        g_yh[n * 32 + cq * 2 + 0] = __floats2half2_rn(ay[i][0], ay[i][1]);
        g_yh[n * 32 + cq * 2 + 1] = __floats2half2_rn(ay[i][2], ay[i][3]);
    }
    // zero padding: half2 slots 20..31 of each row
    for (int i = tid; i < NODES_BLK * 12; i += GEMM_THREADS) {
        int node = n0 + i / 12;
        int slot = 20 + i % 12;
        if (node < NN) g_yh[node * 32 + slot] = __floats2half2_rn(0.f, 0.f);
    }
}

// ---------------------------------------------------------------------------
__device__ __forceinline__ int load_idx(const void* raw, long long pos) {
    int v;
    if (g_is64) v = (int)((const long long*)raw)[pos];
    else        v = ((const int*)raw)[pos];
    return min(max(v, 0), NN - 1);
}

__global__ void __launch_bounds__(256) k_hist(const void* __restrict__ idx_raw) {
    int e = blockIdx.x * 256 + threadIdx.x;
    if (e >= NE) return;
    atomicAdd(&g_cnt[load_idx(idx_raw, (long long)NE + e)], 1);
}

// K3a: 1024-elem exclusive scan per block (shfl-based)
__global__ void __launch_bounds__(256) k_scan1() {
    __shared__ int s_ws[8];
    __shared__ int s_woff[8];
    int tid = threadIdx.x, lane = tid & 31, w = tid >> 5;
    int base = blockIdx.x * 1024 + tid * 4;
    int v0 = (base + 0 < NN) ? g_cnt[base + 0] : 0;
    int v1 = (base + 1 < NN) ? g_cnt[base + 1] : 0;
    int v2 = (base + 2 < NN) ? g_cnt[base + 2] : 0;
    int v3 = (base + 3 < NN) ? g_cnt[base + 3] : 0;
    int tsum = v0 + v1 + v2 + v3;
    int incl = tsum;
#pragma unroll
    for (int off = 1; off < 32; off <<= 1) {
        int t = __shfl_up_sync(0xFFFFFFFFu, incl, off);
        if (lane >= off) incl += t;
    }
    if (lane == 31) s_ws[w] = incl;
    __syncthreads();
    if (w == 0 && lane < 8) {
        int v = s_ws[lane];
        int inc2 = v;
#pragma unroll
        for (int off = 1; off < 8; off <<= 1) {
            int t = __shfl_up_sync(0xFFu, inc2, off);
            if (lane >= off) inc2 += t;
        }
        s_woff[lane] = inc2 - v;
        if (lane == 7) g_bsums[blockIdx.x] = inc2;
    }
    __syncthreads();
    int excl = incl - tsum + s_woff[w];
    if (base + 0 < NN) g_off[base + 0] = excl;
    if (base + 1 < NN) g_off[base + 1] = excl + v0;
    if (base + 2 < NN) g_off[base + 2] = excl + v0 + v1;
    if (base + 3 < NN) g_off[base + 3] = excl + v0 + v1 + v2;
}

// K3b: scan 98 block sums
__global__ void k_scan2() {
    __shared__ int s[128];
    int tid = threadIdx.x;
    int v = (tid < NBLK_SCAN) ? g_bsums[tid] : 0;
    s[tid] = v;
    __syncthreads();
#pragma unroll
    for (int off = 1; off < 128; off <<= 1) {
        int t = (tid >= off) ? s[tid - off] : 0;
        __syncthreads();
        s[tid] += t;
        __syncthreads();
    }
    if (tid < NBLK_SCAN) g_bsums[tid] = s[tid] - v;
}

// K3c: finalize offsets + init cursors
__global__ void __launch_bounds__(256) k_scan3() {
    int n = blockIdx.x * 256 + threadIdx.x;
    if (n >= NN) return;
    int o = g_off[n] + g_bsums[n >> 10];
    g_off[n] = o;
    g_cursor[n] = o;
}

// K4: CSR fill
__global__ void __launch_bounds__(256) k_fill(const void* __restrict__ idx_raw) {
    int e = blockIdx.x * 256 + threadIdx.x;
    if (e >= NE) return;
    int src = load_idx(idx_raw, e);
    int dst = load_idx(idx_raw, (long long)NE + e);
    g_csr[atomicAdd(&g_cursor[dst], 1)] = src;
}

// ---------------------------------------------------------------------------
// K5: fused gather-mean + z + log_softmax. Warp per node.
// Lane holds columns (2*lane, 2*lane+1); one coalesced 128B line per edge.
// ---------------------------------------------------------------------------
__global__ void __launch_bounds__(256) k_fused(float* __restrict__ out) {
    int gtid = blockIdx.x * 256 + threadIdx.x;
    int node = gtid >> 5;
    int lane = threadIdx.x & 31;
    if (node >= NN) return;

    int base = g_off[node];
    int deg  = g_cnt[node];

    float2 acc = make_float2(0.f, 0.f);
    for (int j0 = 0; j0 < deg; j0 += 32) {
        int e = (j0 + lane < deg) ? g_csr[base + j0 + lane] : 0;
        int m = min(32, deg - j0);
        for (int k = 0; k < m; k++) {
            int src = __shfl_sync(0xFFFFFFFFu, e, k);
            __half2 h = g_yh[src * 32 + lane];
            float2 f = __half22float2(h);
            acc.x += f.x;
            acc.y += f.y;
        }
    }

    float inv = 1.0f / fmaxf((float)deg, 1.0f);
    const float NEG = -3.0e38f;
    bool valid = lane < 20;
    float2 z2 = valid ? reinterpret_cast<const float2*>(&g_z[node * NC])[lane]
                      : make_float2(0.f, 0.f);
    float va = valid ? fmaf(acc.x, inv, z2.x) : NEG;
    float vb = valid ? fmaf(acc.y, inv, z2.y) : NEG;

    float mx = fmaxf(va, vb);
#pragma unroll
    for (int off = 16; off > 0; off >>= 1)
        mx = fmaxf(mx, __shfl_xor_sync(0xFFFFFFFFu, mx, off));

    float s = valid ? (__expf(va - mx) + __expf(vb - mx)) : 0.0f;
#pragma unroll
    for (int off = 16; off > 0; off >>= 1)
        s += __shfl_xor_sync(0xFFFFFFFFu, s, off);

    float lse = mx + logf(s);
    if (valid) {
        float2 o = make_float2(va - lse, vb - lse);
        reinterpret_cast<float2*>(&out[node * NC])[lane] = o;
    }
}

extern "C" void kernel_launch(void* const* d_in, const int* in_sizes, int n_in,
                              void* d_out, int out_size) {
    const float* x   = (const float*)d_in[0];
    const void*  idx = d_in[1];
    const float* wl  = (const float*)d_in[2];
    const float* bl  = (const float*)d_in[3];
    const float* wr  = (const float*)d_in[4];
    float* out = (float*)d_out;

    k_prep<<<(NN + 255) / 256, 256>>>((const int*)idx);
    k_gemm<<<(NN + NODES_BLK - 1) / NODES_BLK, GEMM_THREADS>>>(x, wl, bl, wr);
    k_hist<<<(NE + 255) / 256, 256>>>(idx);
    k_scan1<<<NBLK_SCAN, 256>>>();
    k_scan2<<<1, 128>>>();
    k_scan3<<<(NN + 255) / 256, 256>>>();
    k_fill<<<(NE + 255) / 256, 256>>>(idx);
    k_fused<<<(NN * 32 + 255) / 256, 256>>>(out);
}